// round 1
// baseline (speedup 1.0000x reference)
#include <cuda_runtime.h>
#include <cuda_bf16.h>
#include <math.h>

#define Bv 32
#define Hv 128
#define Wv 128
#define Cv 10
#define Kv 32
#define CH 32

#define A_ELEMS (Bv*Hv*Wv*Kv)      // 16,777,216
#define T_FEATS 17

// -------------------- scratch (static __device__, no allocs) --------------------
__device__ __align__(256) float g_r1 [Bv*Hv*Wv*CH];   // conv1 out; later A ping buffer
__device__ __align__(256) float g_phi[Bv*Hv*Wv*CH];   // conv2+conv3 fused out
__device__ __align__(256) float g_aff[Bv*Hv*Wv*4];    // neighbor affinities
__device__ __align__(256) float g_A0 [Hv*Wv*Kv];      // batch-independent init assignment
__device__ __align__(256) float g_part[Bv*Hv*Kv*13];  // pooling partials per (b,h,k)

// ============================================================================
// conv1: one-hot -> 3x3 conv (10->32) + relu.  Pure table lookup-sum.
// ============================================================================
__global__ __launch_bounds__(256) void conv1_kernel(
    const int* __restrict__ X, const float* __restrict__ w1,
    const float* __restrict__ b1, float* __restrict__ r1)
{
    __shared__ float s_w1[9*Cv*CH];   // 2880 floats
    __shared__ float s_b1[CH];
    __shared__ int   s_x[3][Wv];

    int b = blockIdx.x, h = blockIdx.y;
    int tid = threadIdx.x;

    for (int i = tid; i < 9*Cv*CH; i += 256) s_w1[i] = w1[i];
    if (tid < CH) s_b1[tid] = b1[tid];
    for (int i = tid; i < 3*Wv; i += 256) {
        int r = i / Wv, w = i % Wv;
        int hh = h + r - 1;
        s_x[r][w] = (hh >= 0 && hh < Hv) ? X[(b*Hv + hh)*Wv + w] : -1;
    }
    __syncthreads();

    int co = tid & 31, wl = tid >> 5;
    for (int w = wl; w < Wv; w += 8) {
        float acc = s_b1[co];
        #pragma unroll
        for (int dy = 0; dy < 3; dy++) {
            #pragma unroll
            for (int dx = 0; dx < 3; dx++) {
                int ww = w + dx - 1;
                if (ww < 0 || ww >= Wv) continue;
                int c = s_x[dy][ww];
                if (c >= 0) acc += s_w1[((dy*3+dx)*Cv + c)*CH + co];
            }
        }
        r1[((size_t)((b*Hv + h)*Wv + w))*CH + co] = fmaxf(acc, 0.f);
    }
}

// ============================================================================
// conv2 (3x3, 32->32, relu) fused with conv3 (1x1, 32->32) -> phi.
// Tile 16x16 output pixels per 256-thread block, 85KB dynamic smem.
// ============================================================================
#define S_IN_F   (CH*18*19)        // 10944
#define S_W2_F   (9*CH*CH)         // 9216
#define S_W3_F   (CH*CH)           // 1024
#define CONV23_SMEM ((S_IN_F + S_W2_F + S_W3_F + 64) * 4)

__global__ __launch_bounds__(256) void conv23_kernel(
    const float* __restrict__ r1,
    const float* __restrict__ w2, const float* __restrict__ b2,
    const float* __restrict__ w3, const float* __restrict__ b3,
    float* __restrict__ phi)
{
    extern __shared__ float smem[];
    float* s_in = smem;                       // [ci][18][19]
    float* s_w2 = smem + S_IN_F;              // [pos][ci][co]
    float* s_w3 = s_w2 + S_W2_F;              // [ci][co]
    float* s_b2 = s_w3 + S_W3_F;              // [32]
    float* s_b3 = s_b2 + 32;                  // [32]

    int b = blockIdx.x, h0 = blockIdx.y*16, w0 = blockIdx.z*16;
    int tid = threadIdx.x;

    for (int i = tid; i < S_W2_F; i += 256) s_w2[i] = w2[i];
    for (int i = tid; i < S_W3_F; i += 256) s_w3[i] = w3[i];
    if (tid < 32) { s_b2[tid] = b2[tid]; s_b3[tid] = b3[tid]; }

    // load 18x18 halo tile, transpose NHWC -> [ci][lh][lw]
    for (int p = tid; p < 18*18; p += 256) {
        int lh = p / 18, lw = p % 18;
        int gh = h0 + lh - 1, gw = w0 + lw - 1;
        if (gh >= 0 && gh < Hv && gw >= 0 && gw < Wv) {
            const float4* src = (const float4*)(r1 + (size_t)((b*Hv+gh)*Wv+gw)*CH);
            #pragma unroll
            for (int j = 0; j < 8; j++) {
                float4 v = src[j];
                s_in[(4*j+0)*18*19 + lh*19 + lw] = v.x;
                s_in[(4*j+1)*18*19 + lh*19 + lw] = v.y;
                s_in[(4*j+2)*18*19 + lh*19 + lw] = v.z;
                s_in[(4*j+3)*18*19 + lh*19 + lw] = v.w;
            }
        } else {
            #pragma unroll
            for (int c = 0; c < CH; c++) s_in[c*18*19 + lh*19 + lw] = 0.f;
        }
    }
    __syncthreads();

    int lh = tid >> 4, lw = tid & 15;

    float acc[CH];
    #pragma unroll
    for (int co = 0; co < CH; co++) acc[co] = s_b2[co];

    #pragma unroll
    for (int pos = 0; pos < 9; pos++) {
        int dy = pos / 3, dx = pos % 3;
        const float* in_base = s_in + (lh+dy)*19 + (lw+dx);
        const float* w_base  = s_w2 + pos*CH*CH;
        #pragma unroll 4
        for (int ci = 0; ci < CH; ci++) {
            float v = in_base[ci*18*19];
            const float4* wp = (const float4*)(w_base + ci*CH);
            #pragma unroll
            for (int g = 0; g < 8; g++) {
                float4 wv = wp[g];
                acc[4*g+0] = fmaf(v, wv.x, acc[4*g+0]);
                acc[4*g+1] = fmaf(v, wv.y, acc[4*g+1]);
                acc[4*g+2] = fmaf(v, wv.z, acc[4*g+2]);
                acc[4*g+3] = fmaf(v, wv.w, acc[4*g+3]);
            }
        }
    }

    // relu + fused 1x1 conv3
    float out[CH];
    #pragma unroll
    for (int co = 0; co < CH; co++) { acc[co] = fmaxf(acc[co], 0.f); out[co] = s_b3[co]; }
    #pragma unroll 4
    for (int ci = 0; ci < CH; ci++) {
        float v = acc[ci];
        const float4* wp = (const float4*)(s_w3 + ci*CH);
        #pragma unroll
        for (int g = 0; g < 8; g++) {
            float4 wv = wp[g];
            out[4*g+0] = fmaf(v, wv.x, out[4*g+0]);
            out[4*g+1] = fmaf(v, wv.y, out[4*g+1]);
            out[4*g+2] = fmaf(v, wv.z, out[4*g+2]);
            out[4*g+3] = fmaf(v, wv.w, out[4*g+3]);
        }
    }

    float4* dst = (float4*)(phi + (size_t)((b*Hv + h0+lh)*Wv + w0+lw)*CH);
    #pragma unroll
    for (int g = 0; g < 8; g++)
        dst[g] = make_float4(out[4*g], out[4*g+1], out[4*g+2], out[4*g+3]);
}

// ============================================================================
// neighbor affinity: w[p,d] = exp(-2 * ||phi[p]-phi[nbr_d(p)]||^2) * valid
// nbr under _shift(phi,dh,dw)[h,w] = phi[h-dh, w-dw]:
//   d0:(dh=-1)->phi[h+1,w]  d1:(+1)->phi[h-1,w]  d2:(dw=-1)->phi[h,w+1]  d3:->phi[h,w-1]
// ============================================================================
__device__ __forceinline__ float aff_edge(const float c[CH], const float* __restrict__ nb) {
    float d2 = 0.f;
    const float4* n4 = (const float4*)nb;
    #pragma unroll
    for (int g = 0; g < 8; g++) {
        float4 v = n4[g];
        float a = c[4*g+0] - v.x, b = c[4*g+1] - v.y;
        float e = c[4*g+2] - v.z, f = c[4*g+3] - v.w;
        d2 += a*a + b*b + e*e + f*f;
    }
    return __expf(-2.f * d2);
}

__global__ __launch_bounds__(128) void aff_kernel(
    const float* __restrict__ phi, float* __restrict__ aff)
{
    int bh = blockIdx.x; int b = bh >> 7, h = bh & 127; int w = threadIdx.x;
    size_t pix = (size_t)(b*Hv + h)*Wv + w;
    float c[CH];
    const float4* c4 = (const float4*)(phi + pix*CH);
    #pragma unroll
    for (int g = 0; g < 8; g++) {
        float4 v = c4[g];
        c[4*g+0]=v.x; c[4*g+1]=v.y; c[4*g+2]=v.z; c[4*g+3]=v.w;
    }
    float4 wd;
    wd.x = (h+1 < Hv) ? aff_edge(c, phi + (pix + Wv)*CH) : 0.f;
    wd.y = (h   >= 1) ? aff_edge(c, phi + (pix - Wv)*CH) : 0.f;
    wd.z = (w+1 < Wv) ? aff_edge(c, phi + (pix + 1 )*CH) : 0.f;
    wd.w = (w   >= 1) ? aff_edge(c, phi + (pix - 1 )*CH) : 0.f;
    ((float4*)aff)[pix] = wd;
}

// ============================================================================
// init A0 (batch independent): softmax_k( -d2(h,w;seed_k)/512 )
// seeds: 4x8 grid; seed_h[k]=((k>>3)+0.5)*32, seed_w[k]=((k&7)+0.5)*16; h,w raw indices
// ============================================================================
__global__ __launch_bounds__(128) void initA_kernel(float* __restrict__ A0)
{
    int h = blockIdx.x, w = threadIdx.x;
    float fh = (float)h, fw = (float)w;
    float lg[Kv]; float m = -1e30f;
    #pragma unroll
    for (int k = 0; k < Kv; k++) {
        float sh = ((k >> 3) + 0.5f) * 32.f;
        float sw = ((k & 7)  + 0.5f) * 16.f;
        float dh = fh - sh, dw = fw - sw;
        lg[k] = -(dh*dh + dw*dw) * (1.f/512.f);
        m = fmaxf(m, lg[k]);
    }
    float s = 0.f;
    #pragma unroll
    for (int k = 0; k < Kv; k++) { lg[k] = __expf(lg[k] - m); s += lg[k]; }
    float inv = 1.f / s;
    float4* dst = (float4*)(A0 + (size_t)(h*Wv + w)*Kv);
    #pragma unroll
    for (int g = 0; g < 8; g++)
        dst[g] = make_float4(lg[4*g]*inv, lg[4*g+1]*inv, lg[4*g+2]*inv, lg[4*g+3]*inv);
}

// ============================================================================
// one message-pass iteration:
//   agg[k] = sum_d w[p,d]*Ain[nbr_d(p),k];  Aout = softmax(2*agg) over k
// bstride = Hv*Wv*Kv for batched input, 0 for the shared A0.
// ============================================================================
__device__ __forceinline__ void mp_accum(float agg[Kv], const float* __restrict__ src, float wd) {
    const float4* s4 = (const float4*)src;
    #pragma unroll
    for (int g = 0; g < 8; g++) {
        float4 v = s4[g];
        agg[4*g+0] = fmaf(wd, v.x, agg[4*g+0]);
        agg[4*g+1] = fmaf(wd, v.y, agg[4*g+1]);
        agg[4*g+2] = fmaf(wd, v.z, agg[4*g+2]);
        agg[4*g+3] = fmaf(wd, v.w, agg[4*g+3]);
    }
}

__global__ __launch_bounds__(128) void msgpass_kernel(
    const float* __restrict__ Ain, int bstride,
    const float* __restrict__ aff, float* __restrict__ Aout)
{
    int bh = blockIdx.x; int b = bh >> 7, h = bh & 127; int w = threadIdx.x;
    size_t pix = (size_t)(b*Hv + h)*Wv + w;
    float4 wd = ((const float4*)aff)[pix];

    float agg[Kv];
    #pragma unroll
    for (int k = 0; k < Kv; k++) agg[k] = 0.f;

    const float* base = Ain + (size_t)b * bstride;
    size_t loc = (size_t)h*Wv + w;
    if (h+1 < Hv) mp_accum(agg, base + (loc + Wv)*Kv, wd.x);
    if (h   >= 1) mp_accum(agg, base + (loc - Wv)*Kv, wd.y);
    if (w+1 < Wv) mp_accum(agg, base + (loc + 1 )*Kv, wd.z);
    if (w   >= 1) mp_accum(agg, base + (loc - 1 )*Kv, wd.w);

    float m = -1e30f;
    #pragma unroll
    for (int k = 0; k < Kv; k++) m = fmaxf(m, agg[k]);
    float s = 0.f;
    #pragma unroll
    for (int k = 0; k < Kv; k++) { agg[k] = __expf(2.f*(agg[k] - m)); s += agg[k]; }
    float inv = 1.f / s;
    float4* dst = (float4*)(Aout + pix*Kv);
    #pragma unroll
    for (int g = 0; g < 8; g++)
        dst[g] = make_float4(agg[4*g]*inv, agg[4*g+1]*inv, agg[4*g+2]*inv, agg[4*g+3]*inv);
}

// ============================================================================
// pooling stage 1: per (b,h) row -> partials per (b,h,k): [mass, w_acc, w2_acc, cls0..9]
// Fully deterministic (fixed-order reductions, no atomics).
// ============================================================================
__global__ __launch_bounds__(256) void pool1_kernel(
    const float* __restrict__ A, const int* __restrict__ X, float* __restrict__ part)
{
    __shared__ int   s_x[Wv];
    __shared__ float s_red[3][8][Kv];
    __shared__ float s_cls[8][Kv][Cv];

    int bh = blockIdx.x; int b = bh >> 7, h = bh & 127;
    int tid = threadIdx.x;
    int k = tid & 31, wl = tid >> 5;

    if (tid < Wv) s_x[tid] = X[(b*Hv + h)*Wv + tid];
    __syncthreads();

    float mass = 0.f, wa = 0.f, w2a = 0.f;
    float cls[Cv];
    #pragma unroll
    for (int c = 0; c < Cv; c++) cls[c] = 0.f;

    #pragma unroll 1
    for (int it = 0; it < 16; it++) {
        int w = wl*16 + it;
        float a = A[((size_t)(b*Hv + h)*Wv + w)*Kv + k];
        float fw = (w + 0.5f) * (1.f/128.f);
        mass += a;
        wa  = fmaf(a, fw, wa);
        w2a = fmaf(a, fw*fw, w2a);
        int c = s_x[w];
        #pragma unroll
        for (int cc = 0; cc < Cv; cc++) cls[cc] += (c == cc) ? a : 0.f;
    }
    s_red[0][wl][k] = mass; s_red[1][wl][k] = wa; s_red[2][wl][k] = w2a;
    #pragma unroll
    for (int cc = 0; cc < Cv; cc++) s_cls[wl][k][cc] = cls[cc];
    __syncthreads();

    if (tid < Kv) {
        float m = 0.f, a1 = 0.f, a2 = 0.f, c10[Cv];
        #pragma unroll
        for (int cc = 0; cc < Cv; cc++) c10[cc] = 0.f;
        #pragma unroll
        for (int j = 0; j < 8; j++) {
            m  += s_red[0][j][tid];
            a1 += s_red[1][j][tid];
            a2 += s_red[2][j][tid];
            #pragma unroll
            for (int cc = 0; cc < Cv; cc++) c10[cc] += s_cls[j][tid][cc];
        }
        float* dst = part + ((size_t)(b*Hv + h)*Kv + tid)*13;
        dst[0] = m; dst[1] = a1; dst[2] = a2;
        #pragma unroll
        for (int cc = 0; cc < Cv; cc++) dst[3+cc] = c10[cc];
    }
}

// ============================================================================
// pooling stage 2: reduce over h, emit T (B,K,17)
// ============================================================================
__global__ __launch_bounds__(256) void pool2_kernel(
    const float* __restrict__ part, float* __restrict__ T)
{
    int i = blockIdx.x*blockDim.x + threadIdx.x;
    if (i >= Bv*Kv) return;
    int b = i / Kv, k = i % Kv;

    float macc=0.f, ha=0.f, h2a=0.f, wa=0.f, w2a=0.f, cls[Cv];
    #pragma unroll
    for (int cc = 0; cc < Cv; cc++) cls[cc] = 0.f;

    for (int h = 0; h < Hv; h++) {
        const float* p = part + ((size_t)(b*Hv + h)*Kv + k)*13;
        float m = p[0];
        float fh = (h + 0.5f) * (1.f/128.f);
        macc += m;
        ha  = fmaf(m, fh, ha);
        h2a = fmaf(m, fh*fh, h2a);
        wa  += p[1];
        w2a += p[2];
        #pragma unroll
        for (int cc = 0; cc < Cv; cc++) cls[cc] += p[3+cc];
    }
    float mass = macc + 1e-6f;
    float inv = 1.f / mass;
    float h_c = ha*inv, w_c = wa*inv;
    float h2 = h2a*inv, w2 = w2a*inv;
    float h_sd = sqrtf(fmaxf(h2 - h_c*h_c, 0.f) + 1e-6f);
    float w_sd = sqrtf(fmaxf(w2 - w_c*w_c, 0.f) + 1e-6f);

    float* t = T + (size_t)i * T_FEATS;
    t[0] = mass * (1.f/16384.f);
    t[1] = h_c; t[2] = w_c;
    #pragma unroll
    for (int cc = 0; cc < Cv; cc++) t[3+cc] = cls[cc]*inv;
    t[13] = h_c - h_sd; t[14] = h_c + h_sd;
    t[15] = w_c - w_sd; t[16] = w_c + w_sd;
}

// ============================================================================
// launch
// ============================================================================
extern "C" void kernel_launch(void* const* d_in, const int* in_sizes, int n_in,
                              void* d_out, int out_size)
{
    const int*   X  = (const int*)  d_in[0];
    const float* w1 = (const float*)d_in[1];
    const float* b1 = (const float*)d_in[2];
    const float* w2 = (const float*)d_in[3];
    const float* b2 = (const float*)d_in[4];
    const float* w3 = (const float*)d_in[5];
    const float* b3 = (const float*)d_in[6];

    float* outA = (float*)d_out;                 // (B,H,W,K)
    float* outT = (float*)d_out + A_ELEMS;       // (B,K,17)

    float *r1, *phi, *aff, *A0, *part;
    cudaGetSymbolAddress((void**)&r1,   g_r1);
    cudaGetSymbolAddress((void**)&phi,  g_phi);
    cudaGetSymbolAddress((void**)&aff,  g_aff);
    cudaGetSymbolAddress((void**)&A0,   g_A0);
    cudaGetSymbolAddress((void**)&part, g_part);

    cudaFuncSetAttribute(conv23_kernel, cudaFuncAttributeMaxDynamicSharedMemorySize, CONV23_SMEM);

    conv1_kernel<<<dim3(Bv, Hv), 256>>>(X, w1, b1, r1);
    conv23_kernel<<<dim3(Bv, Hv/16, Wv/16), 256, CONV23_SMEM>>>(r1, w2, b2, w3, b3, phi);
    aff_kernel<<<Bv*Hv, 128>>>(phi, aff);
    initA_kernel<<<Hv, 128>>>(A0);

    // 8 message-pass iterations; even count ends in d_out A region
    msgpass_kernel<<<Bv*Hv, 128>>>(A0,  0,          aff, r1);
    msgpass_kernel<<<Bv*Hv, 128>>>(r1,  Hv*Wv*Kv,   aff, outA);
    msgpass_kernel<<<Bv*Hv, 128>>>(outA, Hv*Wv*Kv,  aff, r1);
    msgpass_kernel<<<Bv*Hv, 128>>>(r1,  Hv*Wv*Kv,   aff, outA);
    msgpass_kernel<<<Bv*Hv, 128>>>(outA, Hv*Wv*Kv,  aff, r1);
    msgpass_kernel<<<Bv*Hv, 128>>>(r1,  Hv*Wv*Kv,   aff, outA);
    msgpass_kernel<<<Bv*Hv, 128>>>(outA, Hv*Wv*Kv,  aff, r1);
    msgpass_kernel<<<Bv*Hv, 128>>>(r1,  Hv*Wv*Kv,   aff, outA);

    pool1_kernel<<<Bv*Hv, 256>>>(outA, X, part);
    pool2_kernel<<<4, 256>>>(part, outT);
}

// round 2
// speedup vs baseline: 1.4684x; 1.4684x over previous
#include <cuda_runtime.h>
#include <cuda_bf16.h>
#include <math.h>

#define Bv 32
#define Hv 128
#define Wv 128
#define Cv 10
#define Kv 32
#define CH 32

#define A_ELEMS (Bv*Hv*Wv*Kv)
#define T_FEATS 17

// -------------------- scratch (static __device__, no allocs) --------------------
__device__ __align__(256) float g_r1 [Bv*Hv*Wv*CH];   // conv1 out; later A ping buffer
__device__ __align__(256) float g_phi[Bv*Hv*Wv*CH];   // conv2+conv3 fused out
__device__ __align__(256) float g_aff[Bv*Hv*Wv*4];    // neighbor affinities
__device__ __align__(256) float g_A0 [Hv*Wv*Kv];      // batch-independent init assignment
__device__ __align__(256) float g_part[Bv*Hv*Kv*13];  // pooling partials per (b,h,k)

// -------------------- f32x2 packed helpers (Blackwell FFMA2) --------------------
__device__ __forceinline__ unsigned long long pack2(float lo, float hi) {
    unsigned long long r;
    asm("mov.b64 %0,{%1,%2};" : "=l"(r) : "f"(lo), "f"(hi));
    return r;
}
__device__ __forceinline__ float2 unpack2(unsigned long long v) {
    float2 r;
    asm("mov.b64 {%0,%1},%2;" : "=f"(r.x), "=f"(r.y) : "l"(v));
    return r;
}
__device__ __forceinline__ void ffma2(unsigned long long &d,
                                      unsigned long long a, unsigned long long b) {
    asm("fma.rn.f32x2 %0, %1, %2, %0;" : "+l"(d) : "l"(a), "l"(b));
}

// ============================================================================
// conv1: one-hot -> 3x3 conv (10->32) + relu.  Pure table lookup-sum.
// ============================================================================
__global__ __launch_bounds__(256) void conv1_kernel(
    const int* __restrict__ X, const float* __restrict__ w1,
    const float* __restrict__ b1, float* __restrict__ r1)
{
    __shared__ float s_w1[9*Cv*CH];
    __shared__ float s_b1[CH];
    __shared__ int   s_x[3][Wv];

    int b = blockIdx.x, h = blockIdx.y;
    int tid = threadIdx.x;

    for (int i = tid; i < 9*Cv*CH; i += 256) s_w1[i] = w1[i];
    if (tid < CH) s_b1[tid] = b1[tid];
    for (int i = tid; i < 3*Wv; i += 256) {
        int r = i / Wv, w = i % Wv;
        int hh = h + r - 1;
        s_x[r][w] = (hh >= 0 && hh < Hv) ? X[(b*Hv + hh)*Wv + w] : -1;
    }
    __syncthreads();

    int co = tid & 31, wl = tid >> 5;
    for (int w = wl; w < Wv; w += 8) {
        float acc = s_b1[co];
        #pragma unroll
        for (int dy = 0; dy < 3; dy++) {
            #pragma unroll
            for (int dx = 0; dx < 3; dx++) {
                int ww = w + dx - 1;
                if (ww < 0 || ww >= Wv) continue;
                int c = s_x[dy][ww];
                if (c >= 0) acc += s_w1[((dy*3+dx)*Cv + c)*CH + co];
            }
        }
        r1[((size_t)((b*Hv + h)*Wv + w))*CH + co] = fmaxf(acc, 0.f);
    }
}

// ============================================================================
// conv2 (3x3, 32->32, relu) fused with conv3 (1x1, 32->32) -> phi.
// f32x2 packed FMA path: 2 fp32 MACs per instruction.
// ============================================================================
#define S_IN_F   (CH*18*19)
#define S_W2_F   (9*CH*CH)
#define S_W3_F   (CH*CH)
#define CONV23_SMEM ((S_IN_F + S_W2_F + S_W3_F + 64) * 4)

__global__ __launch_bounds__(256) void conv23_kernel(
    const float* __restrict__ r1,
    const float* __restrict__ w2, const float* __restrict__ b2,
    const float* __restrict__ w3, const float* __restrict__ b3,
    float* __restrict__ phi)
{
    extern __shared__ float smem[];
    float* s_in = smem;                       // [ci][18][19]
    float* s_w2 = smem + S_IN_F;              // [pos][ci][co]
    float* s_w3 = s_w2 + S_W2_F;              // [ci][co]
    float* s_b2 = s_w3 + S_W3_F;
    float* s_b3 = s_b2 + 32;

    int b = blockIdx.x, h0 = blockIdx.y*16, w0 = blockIdx.z*16;
    int tid = threadIdx.x;

    for (int i = tid; i < S_W2_F; i += 256) s_w2[i] = w2[i];
    for (int i = tid; i < S_W3_F; i += 256) s_w3[i] = w3[i];
    if (tid < 32) { s_b2[tid] = b2[tid]; s_b3[tid] = b3[tid]; }

    for (int p = tid; p < 18*18; p += 256) {
        int lh = p / 18, lw = p % 18;
        int gh = h0 + lh - 1, gw = w0 + lw - 1;
        if (gh >= 0 && gh < Hv && gw >= 0 && gw < Wv) {
            const float4* src = (const float4*)(r1 + (size_t)((b*Hv+gh)*Wv+gw)*CH);
            #pragma unroll
            for (int j = 0; j < 8; j++) {
                float4 v = src[j];
                s_in[(4*j+0)*18*19 + lh*19 + lw] = v.x;
                s_in[(4*j+1)*18*19 + lh*19 + lw] = v.y;
                s_in[(4*j+2)*18*19 + lh*19 + lw] = v.z;
                s_in[(4*j+3)*18*19 + lh*19 + lw] = v.w;
            }
        } else {
            #pragma unroll
            for (int c = 0; c < CH; c++) s_in[c*18*19 + lh*19 + lw] = 0.f;
        }
    }
    __syncthreads();

    int lh = tid >> 4, lw = tid & 15;

    unsigned long long acc2[16];
    #pragma unroll
    for (int g = 0; g < 16; g++) acc2[g] = pack2(s_b2[2*g], s_b2[2*g+1]);

    #pragma unroll
    for (int pos = 0; pos < 9; pos++) {
        int dy = pos / 3, dx = pos % 3;
        const float* in_base = s_in + (lh+dy)*19 + (lw+dx);
        const unsigned long long* w_base =
            (const unsigned long long*)(s_w2 + pos*CH*CH);
        #pragma unroll 4
        for (int ci = 0; ci < CH; ci++) {
            float v = in_base[ci*18*19];
            unsigned long long v2 = pack2(v, v);
            const unsigned long long* wp = w_base + ci*16;
            #pragma unroll
            for (int g = 0; g < 16; g++) ffma2(acc2[g], v2, wp[g]);
        }
    }

    // relu + fused 1x1 conv3 (also f32x2)
    float a[CH];
    #pragma unroll
    for (int g = 0; g < 16; g++) {
        float2 v = unpack2(acc2[g]);
        a[2*g]   = fmaxf(v.x, 0.f);
        a[2*g+1] = fmaxf(v.y, 0.f);
    }
    unsigned long long out2[16];
    #pragma unroll
    for (int g = 0; g < 16; g++) out2[g] = pack2(s_b3[2*g], s_b3[2*g+1]);
    {
        const unsigned long long* w3p = (const unsigned long long*)s_w3;
        #pragma unroll 4
        for (int ci = 0; ci < CH; ci++) {
            unsigned long long v2 = pack2(a[ci], a[ci]);
            const unsigned long long* wp = w3p + ci*16;
            #pragma unroll
            for (int g = 0; g < 16; g++) ffma2(out2[g], v2, wp[g]);
        }
    }

    float4* dst = (float4*)(phi + (size_t)((b*Hv + h0+lh)*Wv + w0+lw)*CH);
    #pragma unroll
    for (int g = 0; g < 8; g++) {
        float2 lo = unpack2(out2[2*g]);
        float2 hi = unpack2(out2[2*g+1]);
        dst[g] = make_float4(lo.x, lo.y, hi.x, hi.y);
    }
}

// ============================================================================
// neighbor affinity: w[p,d] = exp(-2 * ||phi[p]-phi[nbr_d(p)]||^2) * valid
//   d0 -> phi[h+1,w]  d1 -> phi[h-1,w]  d2 -> phi[h,w+1]  d3 -> phi[h,w-1]
// ============================================================================
__device__ __forceinline__ float aff_edge(const float c[CH], const float* __restrict__ nb) {
    float d2 = 0.f;
    const float4* n4 = (const float4*)nb;
    #pragma unroll
    for (int g = 0; g < 8; g++) {
        float4 v = n4[g];
        float a = c[4*g+0] - v.x, b = c[4*g+1] - v.y;
        float e = c[4*g+2] - v.z, f = c[4*g+3] - v.w;
        d2 += a*a + b*b + e*e + f*f;
    }
    return __expf(-2.f * d2);
}

__global__ __launch_bounds__(128) void aff_kernel(
    const float* __restrict__ phi, float* __restrict__ aff)
{
    int bh = blockIdx.x; int b = bh >> 7, h = bh & 127; int w = threadIdx.x;
    size_t pix = (size_t)(b*Hv + h)*Wv + w;
    float c[CH];
    const float4* c4 = (const float4*)(phi + pix*CH);
    #pragma unroll
    for (int g = 0; g < 8; g++) {
        float4 v = c4[g];
        c[4*g+0]=v.x; c[4*g+1]=v.y; c[4*g+2]=v.z; c[4*g+3]=v.w;
    }
    float4 wd;
    wd.x = (h+1 < Hv) ? aff_edge(c, phi + (pix + Wv)*CH) : 0.f;
    wd.y = (h   >= 1) ? aff_edge(c, phi + (pix - Wv)*CH) : 0.f;
    wd.z = (w+1 < Wv) ? aff_edge(c, phi + (pix + 1 )*CH) : 0.f;
    wd.w = (w   >= 1) ? aff_edge(c, phi + (pix - 1 )*CH) : 0.f;
    ((float4*)aff)[pix] = wd;
}

// ============================================================================
// init A0 (batch independent)
// ============================================================================
__global__ __launch_bounds__(128) void initA_kernel(float* __restrict__ A0)
{
    int h = blockIdx.x, w = threadIdx.x;
    float fh = (float)h, fw = (float)w;
    float lg[Kv]; float m = -1e30f;
    #pragma unroll
    for (int k = 0; k < Kv; k++) {
        float sh = ((k >> 3) + 0.5f) * 32.f;
        float sw = ((k & 7)  + 0.5f) * 16.f;
        float dh = fh - sh, dw = fw - sw;
        lg[k] = -(dh*dh + dw*dw) * (1.f/512.f);
        m = fmaxf(m, lg[k]);
    }
    float s = 0.f;
    #pragma unroll
    for (int k = 0; k < Kv; k++) { lg[k] = __expf(lg[k] - m); s += lg[k]; }
    float inv = 1.f / s;
    float4* dst = (float4*)(A0 + (size_t)(h*Wv + w)*Kv);
    #pragma unroll
    for (int g = 0; g < 8; g++)
        dst[g] = make_float4(lg[4*g]*inv, lg[4*g+1]*inv, lg[4*g+2]*inv, lg[4*g+3]*inv);
}

// ============================================================================
// fused 4x message-pass: 16x16 output tile, halo 4 (24x24 load region),
// smem ping-pong in channel-major layout [k][pix]. One gmem round trip per
// 4 iterations instead of 4.
//   agg[k] = wd.x*A[y+1,x,k] + wd.y*A[y-1,x,k] + wd.z*A[y,x+1,k] + wd.w*A[y,x-1,k]
//   A' = softmax(2*agg) over k
// Out-of-image halo is zero-filled; affinity valid-mask zeros keep garbage
// from ever propagating into in-image pixels.
// ============================================================================
#define REG 24
#define REGPIX (REG*REG)           // 576
#define MP4_SMEM ((64*REGPIX + 4*REGPIX) * 4)   // sA + sB + aff = 156672 B

__global__ __launch_bounds__(512) void msgpass4_kernel(
    const float* __restrict__ Ain, int bstride,
    const float* __restrict__ aff, float* __restrict__ Aout)
{
    extern __shared__ float smem[];
    float*  sA    = smem;                    // [32][576]
    float*  sB    = smem + 32*REGPIX;        // [32][576]
    float4* s_aff = (float4*)(smem + 64*REGPIX);  // [576]

    int tid = threadIdx.x;
    int b   = blockIdx.z;
    int g0h = blockIdx.y*16 - 4;
    int g0w = blockIdx.x*16 - 4;

    const float* Abase = Ain + (size_t)b * bstride;

    // load A tile (transpose to channel-major) + aff tile, zero-fill outside
    for (int pix = tid; pix < REGPIX; pix += 512) {
        int y = pix / REG, x = pix % REG;
        int gh = g0h + y, gw = g0w + x;
        if (gh >= 0 && gh < Hv && gw >= 0 && gw < Wv) {
            const float4* src = (const float4*)(Abase + (size_t)(gh*Wv + gw)*Kv);
            #pragma unroll
            for (int g = 0; g < 8; g++) {
                float4 v = src[g];
                sA[(4*g+0)*REGPIX + pix] = v.x;
                sA[(4*g+1)*REGPIX + pix] = v.y;
                sA[(4*g+2)*REGPIX + pix] = v.z;
                sA[(4*g+3)*REGPIX + pix] = v.w;
            }
            s_aff[pix] = ((const float4*)aff)[(size_t)(b*Hv + gh)*Wv + gw];
        } else {
            #pragma unroll
            for (int k = 0; k < Kv; k++) sA[k*REGPIX + pix] = 0.f;
            s_aff[pix] = make_float4(0.f, 0.f, 0.f, 0.f);
        }
    }
    __syncthreads();

    #pragma unroll
    for (int p = 0; p < 4; p++) {
        const float* in  = (p & 1) ? sB : sA;
        float*       out = (p & 1) ? sA : sB;
        int o = p + 1, S = REG - 2*o;
        int n = S * S;
        if (tid < n) {
            int y = o + tid / S, x = o + tid % S;
            int pc = y*REG + x;
            float4 wd = s_aff[pc];
            float agg[Kv];
            #pragma unroll
            for (int k = 0; k < Kv; k++) {
                const float* row = in + k*REGPIX + pc;
                float v = wd.x * row[ REG];
                v = fmaf(wd.y, row[-REG], v);
                v = fmaf(wd.z, row[  1 ], v);
                v = fmaf(wd.w, row[ -1 ], v);
                agg[k] = v;
            }
            float m = -1e30f;
            #pragma unroll
            for (int k = 0; k < Kv; k++) m = fmaxf(m, agg[k]);
            float s = 0.f;
            #pragma unroll
            for (int k = 0; k < Kv; k++) { agg[k] = __expf(2.f*(agg[k] - m)); s += agg[k]; }
            float inv = 1.f / s;
            #pragma unroll
            for (int k = 0; k < Kv; k++) out[k*REGPIX + pc] = agg[k] * inv;
        }
        __syncthreads();
    }

    // final result lives in sA (pass 3 wrote it); write 16x16 interior
    if (tid < 256) {
        int ly = tid >> 4, lx = tid & 15;
        int pc = (4+ly)*REG + (4+lx);
        int gh = g0h + 4 + ly, gw = g0w + 4 + lx;
        float4* dst = (float4*)(Aout + (size_t)((b*Hv + gh)*Wv + gw)*Kv);
        #pragma unroll
        for (int g = 0; g < 8; g++)
            dst[g] = make_float4(sA[(4*g+0)*REGPIX + pc], sA[(4*g+1)*REGPIX + pc],
                                 sA[(4*g+2)*REGPIX + pc], sA[(4*g+3)*REGPIX + pc]);
    }
}

// ============================================================================
// pooling stage 1: per (b,h) row -> partials [mass, w_acc, w2_acc, cls0..9]
// ============================================================================
__global__ __launch_bounds__(256) void pool1_kernel(
    const float* __restrict__ A, const int* __restrict__ X, float* __restrict__ part)
{
    __shared__ int   s_x[Wv];
    __shared__ float s_red[3][8][Kv];
    __shared__ float s_cls[8][Kv][Cv];

    int bh = blockIdx.x; int b = bh >> 7, h = bh & 127;
    int tid = threadIdx.x;
    int k = tid & 31, wl = tid >> 5;

    if (tid < Wv) s_x[tid] = X[(b*Hv + h)*Wv + tid];
    __syncthreads();

    float mass = 0.f, wa = 0.f, w2a = 0.f;
    float cls[Cv];
    #pragma unroll
    for (int c = 0; c < Cv; c++) cls[c] = 0.f;

    #pragma unroll 1
    for (int it = 0; it < 16; it++) {
        int w = wl*16 + it;
        float a = A[((size_t)(b*Hv + h)*Wv + w)*Kv + k];
        float fw = (w + 0.5f) * (1.f/128.f);
        mass += a;
        wa  = fmaf(a, fw, wa);
        w2a = fmaf(a, fw*fw, w2a);
        int c = s_x[w];
        #pragma unroll
        for (int cc = 0; cc < Cv; cc++) cls[cc] += (c == cc) ? a : 0.f;
    }
    s_red[0][wl][k] = mass; s_red[1][wl][k] = wa; s_red[2][wl][k] = w2a;
    #pragma unroll
    for (int cc = 0; cc < Cv; cc++) s_cls[wl][k][cc] = cls[cc];
    __syncthreads();

    if (tid < Kv) {
        float m = 0.f, a1 = 0.f, a2 = 0.f, c10[Cv];
        #pragma unroll
        for (int cc = 0; cc < Cv; cc++) c10[cc] = 0.f;
        #pragma unroll
        for (int j = 0; j < 8; j++) {
            m  += s_red[0][j][tid];
            a1 += s_red[1][j][tid];
            a2 += s_red[2][j][tid];
            #pragma unroll
            for (int cc = 0; cc < Cv; cc++) c10[cc] += s_cls[j][tid][cc];
        }
        float* dst = part + ((size_t)(b*Hv + h)*Kv + tid)*13;
        dst[0] = m; dst[1] = a1; dst[2] = a2;
        #pragma unroll
        for (int cc = 0; cc < Cv; cc++) dst[3+cc] = c10[cc];
    }
}

// ============================================================================
// pooling stage 2: reduce over h, emit T (B,K,17)
// ============================================================================
__global__ __launch_bounds__(256) void pool2_kernel(
    const float* __restrict__ part, float* __restrict__ T)
{
    int i = blockIdx.x*blockDim.x + threadIdx.x;
    if (i >= Bv*Kv) return;
    int b = i / Kv, k = i % Kv;

    float macc=0.f, ha=0.f, h2a=0.f, wa=0.f, w2a=0.f, cls[Cv];
    #pragma unroll
    for (int cc = 0; cc < Cv; cc++) cls[cc] = 0.f;

    for (int h = 0; h < Hv; h++) {
        const float* p = part + ((size_t)(b*Hv + h)*Kv + k)*13;
        float m = p[0];
        float fh = (h + 0.5f) * (1.f/128.f);
        macc += m;
        ha  = fmaf(m, fh, ha);
        h2a = fmaf(m, fh*fh, h2a);
        wa  += p[1];
        w2a += p[2];
        #pragma unroll
        for (int cc = 0; cc < Cv; cc++) cls[cc] += p[3+cc];
    }
    float mass = macc + 1e-6f;
    float inv = 1.f / mass;
    float h_c = ha*inv, w_c = wa*inv;
    float h2 = h2a*inv, w2 = w2a*inv;
    float h_sd = sqrtf(fmaxf(h2 - h_c*h_c, 0.f) + 1e-6f);
    float w_sd = sqrtf(fmaxf(w2 - w_c*w_c, 0.f) + 1e-6f);

    float* t = T + (size_t)i * T_FEATS;
    t[0] = mass * (1.f/16384.f);
    t[1] = h_c; t[2] = w_c;
    #pragma unroll
    for (int cc = 0; cc < Cv; cc++) t[3+cc] = cls[cc]*inv;
    t[13] = h_c - h_sd; t[14] = h_c + h_sd;
    t[15] = w_c - w_sd; t[16] = w_c + w_sd;
}

// ============================================================================
// launch
// ============================================================================
extern "C" void kernel_launch(void* const* d_in, const int* in_sizes, int n_in,
                              void* d_out, int out_size)
{
    const int*   X  = (const int*)  d_in[0];
    const float* w1 = (const float*)d_in[1];
    const float* b1 = (const float*)d_in[2];
    const float* w2 = (const float*)d_in[3];
    const float* b2 = (const float*)d_in[4];
    const float* w3 = (const float*)d_in[5];
    const float* b3 = (const float*)d_in[6];

    float* outA = (float*)d_out;
    float* outT = (float*)d_out + A_ELEMS;

    float *r1, *phi, *aff, *A0, *part;
    cudaGetSymbolAddress((void**)&r1,   g_r1);
    cudaGetSymbolAddress((void**)&phi,  g_phi);
    cudaGetSymbolAddress((void**)&aff,  g_aff);
    cudaGetSymbolAddress((void**)&A0,   g_A0);
    cudaGetSymbolAddress((void**)&part, g_part);

    cudaFuncSetAttribute(conv23_kernel,   cudaFuncAttributeMaxDynamicSharedMemorySize, CONV23_SMEM);
    cudaFuncSetAttribute(msgpass4_kernel, cudaFuncAttributeMaxDynamicSharedMemorySize, MP4_SMEM);

    conv1_kernel<<<dim3(Bv, Hv), 256>>>(X, w1, b1, r1);
    conv23_kernel<<<dim3(Bv, Hv/16, Wv/16), 256, CONV23_SMEM>>>(r1, w2, b2, w3, b3, phi);
    aff_kernel<<<Bv*Hv, 128>>>(phi, aff);
    initA_kernel<<<Hv, 128>>>(A0);

    // 8 message-pass iterations = 2 fused-by-4 kernels
    msgpass4_kernel<<<dim3(Wv/16, Hv/16, Bv), 512, MP4_SMEM>>>(A0, 0,        aff, r1);
    msgpass4_kernel<<<dim3(Wv/16, Hv/16, Bv), 512, MP4_SMEM>>>(r1, Hv*Wv*Kv, aff, outA);

    pool1_kernel<<<Bv*Hv, 256>>>(outA, X, part);
    pool2_kernel<<<4, 256>>>(part, outT);
}

// round 3
// speedup vs baseline: 1.5033x; 1.0238x over previous
#include <cuda_runtime.h>
#include <cuda_bf16.h>
#include <math.h>

#define Bv 32
#define Hv 128
#define Wv 128
#define Cv 10
#define Kv 32
#define CH 32

#define A_ELEMS (Bv*Hv*Wv*Kv)
#define T_FEATS 17

// -------------------- scratch (static __device__, no allocs) --------------------
__device__ __align__(256) float g_r1 [Bv*Hv*Wv*CH];   // conv1 out; later A ping buffer
__device__ __align__(256) float g_phi[Bv*Hv*Wv*CH];   // conv2+conv3 out; later A ping buffer
__device__ __align__(256) float g_aff[Bv*Hv*Wv*4];    // neighbor affinities
__device__ __align__(256) float g_A0 [Hv*Wv*Kv];      // batch-independent init assignment
__device__ __align__(256) float g_part[Bv*Hv*Kv*13];  // pooling partials per (b,h,k)

// -------------------- f32x2 packed helpers (Blackwell FFMA2) --------------------
__device__ __forceinline__ unsigned long long pack2(float lo, float hi) {
    unsigned long long r;
    asm("mov.b64 %0,{%1,%2};" : "=l"(r) : "f"(lo), "f"(hi));
    return r;
}
__device__ __forceinline__ float2 unpack2(unsigned long long v) {
    float2 r;
    asm("mov.b64 {%0,%1},%2;" : "=f"(r.x), "=f"(r.y) : "l"(v));
    return r;
}
__device__ __forceinline__ void ffma2(unsigned long long &d,
                                      unsigned long long a, unsigned long long b) {
    asm("fma.rn.f32x2 %0, %1, %2, %0;" : "+l"(d) : "l"(a), "l"(b));
}

// ============================================================================
// conv1: one-hot -> 3x3 conv (10->32) + relu.  Pure table lookup-sum.
// ============================================================================
__global__ __launch_bounds__(256) void conv1_kernel(
    const int* __restrict__ X, const float* __restrict__ w1,
    const float* __restrict__ b1, float* __restrict__ r1)
{
    __shared__ float s_w1[9*Cv*CH];
    __shared__ float s_b1[CH];
    __shared__ int   s_x[3][Wv];

    int b = blockIdx.x, h = blockIdx.y;
    int tid = threadIdx.x;

    for (int i = tid; i < 9*Cv*CH; i += 256) s_w1[i] = w1[i];
    if (tid < CH) s_b1[tid] = b1[tid];
    for (int i = tid; i < 3*Wv; i += 256) {
        int r = i / Wv, w = i % Wv;
        int hh = h + r - 1;
        s_x[r][w] = (hh >= 0 && hh < Hv) ? X[(b*Hv + hh)*Wv + w] : -1;
    }
    __syncthreads();

    int co = tid & 31, wl = tid >> 5;
    for (int w = wl; w < Wv; w += 8) {
        float acc = s_b1[co];
        #pragma unroll
        for (int dy = 0; dy < 3; dy++) {
            #pragma unroll
            for (int dx = 0; dx < 3; dx++) {
                int ww = w + dx - 1;
                if (ww < 0 || ww >= Wv) continue;
                int c = s_x[dy][ww];
                if (c >= 0) acc += s_w1[((dy*3+dx)*Cv + c)*CH + co];
            }
        }
        r1[((size_t)((b*Hv + h)*Wv + w))*CH + co] = fmaxf(acc, 0.f);
    }
}

// ============================================================================
// conv2 (3x3, 32->32, relu) fused with conv3 (1x1, 32->32) -> phi.
// f32x2 packed FMA + 128-bit weight loads (2 FFMA2 per LDS.128).
// ============================================================================
#define S_IN_F   (CH*18*19)
#define S_W2_F   (9*CH*CH)
#define S_W3_F   (CH*CH)
#define CONV23_SMEM ((S_IN_F + S_W2_F + S_W3_F + 64) * 4)

__global__ __launch_bounds__(256) void conv23_kernel(
    const float* __restrict__ r1,
    const float* __restrict__ w2, const float* __restrict__ b2,
    const float* __restrict__ w3, const float* __restrict__ b3,
    float* __restrict__ phi)
{
    extern __shared__ float smem[];
    float* s_in = smem;                       // [ci][18][19]
    float* s_w2 = smem + S_IN_F;              // [pos][ci][co]
    float* s_w3 = s_w2 + S_W2_F;              // [ci][co]
    float* s_b2 = s_w3 + S_W3_F;
    float* s_b3 = s_b2 + 32;

    int b = blockIdx.x, h0 = blockIdx.y*16, w0 = blockIdx.z*16;
    int tid = threadIdx.x;

    for (int i = tid; i < S_W2_F; i += 256) s_w2[i] = w2[i];
    for (int i = tid; i < S_W3_F; i += 256) s_w3[i] = w3[i];
    if (tid < 32) { s_b2[tid] = b2[tid]; s_b3[tid] = b3[tid]; }

    for (int p = tid; p < 18*18; p += 256) {
        int lh = p / 18, lw = p % 18;
        int gh = h0 + lh - 1, gw = w0 + lw - 1;
        if (gh >= 0 && gh < Hv && gw >= 0 && gw < Wv) {
            const float4* src = (const float4*)(r1 + (size_t)((b*Hv+gh)*Wv+gw)*CH);
            #pragma unroll
            for (int j = 0; j < 8; j++) {
                float4 v = src[j];
                s_in[(4*j+0)*18*19 + lh*19 + lw] = v.x;
                s_in[(4*j+1)*18*19 + lh*19 + lw] = v.y;
                s_in[(4*j+2)*18*19 + lh*19 + lw] = v.z;
                s_in[(4*j+3)*18*19 + lh*19 + lw] = v.w;
            }
        } else {
            #pragma unroll
            for (int c = 0; c < CH; c++) s_in[c*18*19 + lh*19 + lw] = 0.f;
        }
    }
    __syncthreads();

    int lh = tid >> 4, lw = tid & 15;

    unsigned long long acc2[16];
    #pragma unroll
    for (int g = 0; g < 16; g++) acc2[g] = pack2(s_b2[2*g], s_b2[2*g+1]);

    #pragma unroll
    for (int pos = 0; pos < 9; pos++) {
        int dy = pos / 3, dx = pos % 3;
        const float* in_base = s_in + (lh+dy)*19 + (lw+dx);
        const ulonglong2* w_base = (const ulonglong2*)(s_w2 + pos*CH*CH);
        #pragma unroll 4
        for (int ci = 0; ci < CH; ci++) {
            float v = in_base[ci*18*19];
            unsigned long long v2 = pack2(v, v);
            const ulonglong2* wp = w_base + ci*8;
            #pragma unroll
            for (int g = 0; g < 8; g++) {
                ulonglong2 wv = wp[g];
                ffma2(acc2[2*g],   v2, wv.x);
                ffma2(acc2[2*g+1], v2, wv.y);
            }
        }
    }

    // relu + fused 1x1 conv3 (also f32x2, 128-bit weight loads)
    float a[CH];
    #pragma unroll
    for (int g = 0; g < 16; g++) {
        float2 v = unpack2(acc2[g]);
        a[2*g]   = fmaxf(v.x, 0.f);
        a[2*g+1] = fmaxf(v.y, 0.f);
    }
    unsigned long long out2[16];
    #pragma unroll
    for (int g = 0; g < 16; g++) out2[g] = pack2(s_b3[2*g], s_b3[2*g+1]);
    {
        const ulonglong2* w3p = (const ulonglong2*)s_w3;
        #pragma unroll 4
        for (int ci = 0; ci < CH; ci++) {
            unsigned long long v2 = pack2(a[ci], a[ci]);
            const ulonglong2* wp = w3p + ci*8;
            #pragma unroll
            for (int g = 0; g < 8; g++) {
                ulonglong2 wv = wp[g];
                ffma2(out2[2*g],   v2, wv.x);
                ffma2(out2[2*g+1], v2, wv.y);
            }
        }
    }

    float4* dst = (float4*)(phi + (size_t)((b*Hv + h0+lh)*Wv + w0+lw)*CH);
    #pragma unroll
    for (int g = 0; g < 8; g++) {
        float2 lo = unpack2(out2[2*g]);
        float2 hi = unpack2(out2[2*g+1]);
        dst[g] = make_float4(lo.x, lo.y, hi.x, hi.y);
    }
}

// ============================================================================
// neighbor affinity
// ============================================================================
__device__ __forceinline__ float aff_edge(const float c[CH], const float* __restrict__ nb) {
    float d2 = 0.f;
    const float4* n4 = (const float4*)nb;
    #pragma unroll
    for (int g = 0; g < 8; g++) {
        float4 v = n4[g];
        float a = c[4*g+0] - v.x, b = c[4*g+1] - v.y;
        float e = c[4*g+2] - v.z, f = c[4*g+3] - v.w;
        d2 += a*a + b*b + e*e + f*f;
    }
    return __expf(-2.f * d2);
}

__global__ __launch_bounds__(128) void aff_kernel(
    const float* __restrict__ phi, float* __restrict__ aff)
{
    int bh = blockIdx.x; int b = bh >> 7, h = bh & 127; int w = threadIdx.x;
    size_t pix = (size_t)(b*Hv + h)*Wv + w;
    float c[CH];
    const float4* c4 = (const float4*)(phi + pix*CH);
    #pragma unroll
    for (int g = 0; g < 8; g++) {
        float4 v = c4[g];
        c[4*g+0]=v.x; c[4*g+1]=v.y; c[4*g+2]=v.z; c[4*g+3]=v.w;
    }
    float4 wd;
    wd.x = (h+1 < Hv) ? aff_edge(c, phi + (pix + Wv)*CH) : 0.f;
    wd.y = (h   >= 1) ? aff_edge(c, phi + (pix - Wv)*CH) : 0.f;
    wd.z = (w+1 < Wv) ? aff_edge(c, phi + (pix + 1 )*CH) : 0.f;
    wd.w = (w   >= 1) ? aff_edge(c, phi + (pix - 1 )*CH) : 0.f;
    ((float4*)aff)[pix] = wd;
}

// ============================================================================
// init A0 (batch independent)
// ============================================================================
__global__ __launch_bounds__(128) void initA_kernel(float* __restrict__ A0)
{
    int h = blockIdx.x, w = threadIdx.x;
    float fh = (float)h, fw = (float)w;
    float lg[Kv]; float m = -1e30f;
    #pragma unroll
    for (int k = 0; k < Kv; k++) {
        float sh = ((k >> 3) + 0.5f) * 32.f;
        float sw = ((k & 7)  + 0.5f) * 16.f;
        float dh = fh - sh, dw = fw - sw;
        lg[k] = -(dh*dh + dw*dw) * (1.f/512.f);
        m = fmaxf(m, lg[k]);
    }
    float s = 0.f;
    #pragma unroll
    for (int k = 0; k < Kv; k++) { lg[k] = __expf(lg[k] - m); s += lg[k]; }
    float inv = 1.f / s;
    float4* dst = (float4*)(A0 + (size_t)(h*Wv + w)*Kv);
    #pragma unroll
    for (int g = 0; g < 8; g++)
        dst[g] = make_float4(lg[4*g]*inv, lg[4*g+1]*inv, lg[4*g+2]*inv, lg[4*g+3]*inv);
}

// ============================================================================
// fused 2x message-pass: 16x16 output tile, halo 2 (20x20 region), 109KB smem
// -> 2 blocks/SM. Pass 1 reads smem and writes its registers DIRECTLY to gmem.
// Softmax has no max-subtraction: agg in [0,4] so exp(2*agg) <= e^8, safe.
// ============================================================================
#define REG 20
#define REGPIX (REG*REG)           // 400
#define MP2_SMEM ((64*REGPIX + 4*REGPIX) * 4)   // 108800 B

__global__ __launch_bounds__(512, 2) void msgpass2_kernel(
    const float* __restrict__ Ain, int bstride,
    const float* __restrict__ aff, float* __restrict__ Aout)
{
    extern __shared__ float smem[];
    float*  sA    = smem;                          // [32][400]
    float*  sB    = smem + 32*REGPIX;              // [32][400]
    float4* s_aff = (float4*)(smem + 64*REGPIX);   // [400]

    int tid = threadIdx.x;
    int b   = blockIdx.z;
    int g0h = blockIdx.y*16 - 2;
    int g0w = blockIdx.x*16 - 2;

    const float* Abase = Ain + (size_t)b * bstride;

    for (int pix = tid; pix < REGPIX; pix += 512) {
        int y = pix / REG, x = pix % REG;
        int gh = g0h + y, gw = g0w + x;
        if (gh >= 0 && gh < Hv && gw >= 0 && gw < Wv) {
            const float4* src = (const float4*)(Abase + (size_t)(gh*Wv + gw)*Kv);
            #pragma unroll
            for (int g = 0; g < 8; g++) {
                float4 v = src[g];
                sA[(4*g+0)*REGPIX + pix] = v.x;
                sA[(4*g+1)*REGPIX + pix] = v.y;
                sA[(4*g+2)*REGPIX + pix] = v.z;
                sA[(4*g+3)*REGPIX + pix] = v.w;
            }
            s_aff[pix] = ((const float4*)aff)[(size_t)(b*Hv + gh)*Wv + gw];
        } else {
            #pragma unroll
            for (int k = 0; k < Kv; k++) sA[k*REGPIX + pix] = 0.f;
            s_aff[pix] = make_float4(0.f, 0.f, 0.f, 0.f);
        }
    }
    __syncthreads();

    // ---- pass 0: offset 1, 18x18 region, sA -> sB ----
    if (tid < 18*18) {
        int y = 1 + tid / 18, x = 1 + tid % 18;
        int pc = y*REG + x;
        float4 wd = s_aff[pc];
        float ex[Kv]; float s = 0.f;
        #pragma unroll
        for (int k = 0; k < Kv; k++) {
            const float* row = sA + k*REGPIX + pc;
            float v = wd.x * row[ REG];
            v = fmaf(wd.y, row[-REG], v);
            v = fmaf(wd.z, row[  1 ], v);
            v = fmaf(wd.w, row[ -1 ], v);
            float e = __expf(2.f * v);
            ex[k] = e; s += e;
        }
        float inv = __fdividef(1.f, s);
        #pragma unroll
        for (int k = 0; k < Kv; k++) sB[k*REGPIX + pc] = ex[k] * inv;
    }
    __syncthreads();

    // ---- pass 1: offset 2, 16x16 interior, sB -> gmem (registers direct) ----
    if (tid < 256) {
        int ly = tid >> 4, lx = tid & 15;
        int pc = (2+ly)*REG + (2+lx);
        float4 wd = s_aff[pc];
        float ex[Kv]; float s = 0.f;
        #pragma unroll
        for (int k = 0; k < Kv; k++) {
            const float* row = sB + k*REGPIX + pc;
            float v = wd.x * row[ REG];
            v = fmaf(wd.y, row[-REG], v);
            v = fmaf(wd.z, row[  1 ], v);
            v = fmaf(wd.w, row[ -1 ], v);
            float e = __expf(2.f * v);
            ex[k] = e; s += e;
        }
        float inv = __fdividef(1.f, s);
        int gh = g0h + 2 + ly, gw = g0w + 2 + lx;
        float4* dst = (float4*)(Aout + (size_t)((b*Hv + gh)*Wv + gw)*Kv);
        #pragma unroll
        for (int g = 0; g < 8; g++)
            dst[g] = make_float4(ex[4*g]*inv, ex[4*g+1]*inv, ex[4*g+2]*inv, ex[4*g+3]*inv);
    }
}

// ============================================================================
// pooling stage 1: per (b,h) row -> partials [mass, w_acc, w2_acc, cls0..9]
// ============================================================================
__global__ __launch_bounds__(256) void pool1_kernel(
    const float* __restrict__ A, const int* __restrict__ X, float* __restrict__ part)
{
    __shared__ int   s_x[Wv];
    __shared__ float s_red[3][8][Kv];
    __shared__ float s_cls[8][Kv][Cv];

    int bh = blockIdx.x; int b = bh >> 7, h = bh & 127;
    int tid = threadIdx.x;
    int k = tid & 31, wl = tid >> 5;

    if (tid < Wv) s_x[tid] = X[(b*Hv + h)*Wv + tid];
    __syncthreads();

    float mass = 0.f, wa = 0.f, w2a = 0.f;
    float cls[Cv];
    #pragma unroll
    for (int c = 0; c < Cv; c++) cls[c] = 0.f;

    #pragma unroll 1
    for (int it = 0; it < 16; it++) {
        int w = wl*16 + it;
        float a = A[((size_t)(b*Hv + h)*Wv + w)*Kv + k];
        float fw = (w + 0.5f) * (1.f/128.f);
        mass += a;
        wa  = fmaf(a, fw, wa);
        w2a = fmaf(a, fw*fw, w2a);
        int c = s_x[w];
        #pragma unroll
        for (int cc = 0; cc < Cv; cc++) cls[cc] += (c == cc) ? a : 0.f;
    }
    s_red[0][wl][k] = mass; s_red[1][wl][k] = wa; s_red[2][wl][k] = w2a;
    #pragma unroll
    for (int cc = 0; cc < Cv; cc++) s_cls[wl][k][cc] = cls[cc];
    __syncthreads();

    if (tid < Kv) {
        float m = 0.f, a1 = 0.f, a2 = 0.f, c10[Cv];
        #pragma unroll
        for (int cc = 0; cc < Cv; cc++) c10[cc] = 0.f;
        #pragma unroll
        for (int j = 0; j < 8; j++) {
            m  += s_red[0][j][tid];
            a1 += s_red[1][j][tid];
            a2 += s_red[2][j][tid];
            #pragma unroll
            for (int cc = 0; cc < Cv; cc++) c10[cc] += s_cls[j][tid][cc];
        }
        float* dst = part + ((size_t)(b*Hv + h)*Kv + tid)*13;
        dst[0] = m; dst[1] = a1; dst[2] = a2;
        #pragma unroll
        for (int cc = 0; cc < Cv; cc++) dst[3+cc] = c10[cc];
    }
}

// ============================================================================
// pooling stage 2: reduce over h, emit T (B,K,17)
// ============================================================================
__global__ __launch_bounds__(256) void pool2_kernel(
    const float* __restrict__ part, float* __restrict__ T)
{
    int i = blockIdx.x*blockDim.x + threadIdx.x;
    if (i >= Bv*Kv) return;
    int b = i / Kv, k = i % Kv;

    float macc=0.f, ha=0.f, h2a=0.f, wa=0.f, w2a=0.f, cls[Cv];
    #pragma unroll
    for (int cc = 0; cc < Cv; cc++) cls[cc] = 0.f;

    for (int h = 0; h < Hv; h++) {
        const float* p = part + ((size_t)(b*Hv + h)*Kv + k)*13;
        float m = p[0];
        float fh = (h + 0.5f) * (1.f/128.f);
        macc += m;
        ha  = fmaf(m, fh, ha);
        h2a = fmaf(m, fh*fh, h2a);
        wa  += p[1];
        w2a += p[2];
        #pragma unroll
        for (int cc = 0; cc < Cv; cc++) cls[cc] += p[3+cc];
    }
    float mass = macc + 1e-6f;
    float inv = 1.f / mass;
    float h_c = ha*inv, w_c = wa*inv;
    float h2 = h2a*inv, w2 = w2a*inv;
    float h_sd = sqrtf(fmaxf(h2 - h_c*h_c, 0.f) + 1e-6f);
    float w_sd = sqrtf(fmaxf(w2 - w_c*w_c, 0.f) + 1e-6f);

    float* t = T + (size_t)i * T_FEATS;
    t[0] = mass * (1.f/16384.f);
    t[1] = h_c; t[2] = w_c;
    #pragma unroll
    for (int cc = 0; cc < Cv; cc++) t[3+cc] = cls[cc]*inv;
    t[13] = h_c - h_sd; t[14] = h_c + h_sd;
    t[15] = w_c - w_sd; t[16] = w_c + w_sd;
}

// ============================================================================
// launch
// ============================================================================
extern "C" void kernel_launch(void* const* d_in, const int* in_sizes, int n_in,
                              void* d_out, int out_size)
{
    const int*   X  = (const int*)  d_in[0];
    const float* w1 = (const float*)d_in[1];
    const float* b1 = (const float*)d_in[2];
    const float* w2 = (const float*)d_in[3];
    const float* b2 = (const float*)d_in[4];
    const float* w3 = (const float*)d_in[5];
    const float* b3 = (const float*)d_in[6];

    float* outA = (float*)d_out;
    float* outT = (float*)d_out + A_ELEMS;

    float *r1, *phi, *aff, *A0, *part;
    cudaGetSymbolAddress((void**)&r1,   g_r1);
    cudaGetSymbolAddress((void**)&phi,  g_phi);
    cudaGetSymbolAddress((void**)&aff,  g_aff);
    cudaGetSymbolAddress((void**)&A0,   g_A0);
    cudaGetSymbolAddress((void**)&part, g_part);

    cudaFuncSetAttribute(conv23_kernel,   cudaFuncAttributeMaxDynamicSharedMemorySize, CONV23_SMEM);
    cudaFuncSetAttribute(msgpass2_kernel, cudaFuncAttributeMaxDynamicSharedMemorySize, MP2_SMEM);

    conv1_kernel<<<dim3(Bv, Hv), 256>>>(X, w1, b1, r1);
    conv23_kernel<<<dim3(Bv, Hv/16, Wv/16), 256, CONV23_SMEM>>>(r1, w2, b2, w3, b3, phi);
    aff_kernel<<<Bv*Hv, 128>>>(phi, aff);
    initA_kernel<<<Hv, 128>>>(A0);

    // 8 message-pass iterations = 4 fused-by-2 kernels (phi is free as a ping buffer)
    dim3 mpg(Wv/16, Hv/16, Bv);
    msgpass2_kernel<<<mpg, 512, MP2_SMEM>>>(A0,  0,         aff, r1);
    msgpass2_kernel<<<mpg, 512, MP2_SMEM>>>(r1,  Hv*Wv*Kv,  aff, phi);
    msgpass2_kernel<<<mpg, 512, MP2_SMEM>>>(phi, Hv*Wv*Kv,  aff, r1);
    msgpass2_kernel<<<mpg, 512, MP2_SMEM>>>(r1,  Hv*Wv*Kv,  aff, outA);

    pool1_kernel<<<Bv*Hv, 256>>>(outA, X, part);
    pool2_kernel<<<4, 256>>>(part, outT);
}

// round 4
// speedup vs baseline: 1.6781x; 1.1162x over previous
#include <cuda_runtime.h>
#include <cuda_bf16.h>
#include <math.h>

#define Bv 32
#define Hv 128
#define Wv 128
#define Cv 10
#define Kv 32
#define CH 32

#define A_ELEMS (Bv*Hv*Wv*Kv)
#define T_FEATS 17

// -------------------- scratch (static __device__, no allocs) --------------------
__device__ __align__(256) float g_r1 [Bv*Hv*Wv*CH];   // A ping buffer
__device__ __align__(256) float g_phi[Bv*Hv*Wv*CH];   // phi; later A ping buffer
__device__ __align__(256) float g_aff[Bv*Hv*Wv*4];    // 2x-scaled neighbor affinities
__device__ __align__(256) float g_A0 [Hv*Wv*Kv];      // batch-independent init assignment
__device__ __align__(256) float g_part[Bv*Hv*Kv*13];  // pooling partials per (b,h,k)

// -------------------- f32x2 packed helpers (Blackwell FFMA2) --------------------
__device__ __forceinline__ unsigned long long pack2(float lo, float hi) {
    unsigned long long r;
    asm("mov.b64 %0,{%1,%2};" : "=l"(r) : "f"(lo), "f"(hi));
    return r;
}
__device__ __forceinline__ float2 unpack2(unsigned long long v) {
    float2 r;
    asm("mov.b64 {%0,%1},%2;" : "=f"(r.x), "=f"(r.y) : "l"(v));
    return r;
}
__device__ __forceinline__ void ffma2(unsigned long long &d,
                                      unsigned long long a, unsigned long long b) {
    asm("fma.rn.f32x2 %0, %1, %2, %0;" : "+l"(d) : "l"(a), "l"(b));
}
__device__ __forceinline__ unsigned long long mul2(unsigned long long a, unsigned long long b) {
    unsigned long long r;
    asm("mul.rn.f32x2 %0, %1, %2;" : "=l"(r) : "l"(a), "l"(b));
    return r;
}

// ============================================================================
// init A0 (batch independent) — launched FIRST so ncu -s 5 lands on msgpass
// ============================================================================
__global__ __launch_bounds__(128) void initA_kernel(float* __restrict__ A0)
{
    int h = blockIdx.x, w = threadIdx.x;
    float fh = (float)h, fw = (float)w;
    float lg[Kv]; float m = -1e30f;
    #pragma unroll
    for (int k = 0; k < Kv; k++) {
        float sh = ((k >> 3) + 0.5f) * 32.f;
        float sw = ((k & 7)  + 0.5f) * 16.f;
        float dh = fh - sh, dw = fw - sw;
        lg[k] = -(dh*dh + dw*dw) * (1.f/512.f);
        m = fmaxf(m, lg[k]);
    }
    float s = 0.f;
    #pragma unroll
    for (int k = 0; k < Kv; k++) { lg[k] = __expf(lg[k] - m); s += lg[k]; }
    float inv = 1.f / s;
    float4* dst = (float4*)(A0 + (size_t)(h*Wv + w)*Kv);
    #pragma unroll
    for (int g = 0; g < 8; g++)
        dst[g] = make_float4(lg[4*g]*inv, lg[4*g+1]*inv, lg[4*g+2]*inv, lg[4*g+3]*inv);
}

// ============================================================================
// fully fused conv1 (3x3,10->32 lookup) + conv2 (3x3,32->32) + conv3 (1x1) -> phi
// 16x16 output tile; r1 lives only in smem (18x18 halo), X tile 20x20.
// ============================================================================
#define R1PITCH 343                       // 18*19+1, odd-ish for bank spread
#define OFF_W1  0                         // 2880
#define OFF_B1  (OFF_W1 + 9*Cv*CH)        // 2880
#define OFF_W2  (OFF_B1 + 32)             // 2912
#define OFF_W3  (OFF_W2 + 9*CH*CH)        // 12128
#define OFF_B2  (OFF_W3 + CH*CH)          // 13152
#define OFF_B3  (OFF_B2 + 32)             // 13184
#define OFF_X   (OFF_B3 + 32)             // 13216 (400 ints)
#define OFF_R1  (OFF_X + 400)             // 13616
#define CONV_F  (OFF_R1 + CH*R1PITCH)     // 24592 floats
#define CONV_SMEM (CONV_F * 4)            // 98368 B

__global__ __launch_bounds__(256) void conv123_kernel(
    const int* __restrict__ X,
    const float* __restrict__ w1, const float* __restrict__ b1,
    const float* __restrict__ w2, const float* __restrict__ b2,
    const float* __restrict__ w3, const float* __restrict__ b3,
    float* __restrict__ phi)
{
    extern __shared__ float smem[];
    float* s_w1 = smem + OFF_W1;
    float* s_b1 = smem + OFF_B1;
    float* s_w2 = smem + OFF_W2;
    float* s_w3 = smem + OFF_W3;
    float* s_b2 = smem + OFF_B2;
    float* s_b3 = smem + OFF_B3;
    int*   s_x  = (int*)(smem + OFF_X);   // [20][20]
    float* s_r1 = smem + OFF_R1;          // [32][343] pitch

    int b = blockIdx.x, h0 = blockIdx.y*16, w0 = blockIdx.z*16;
    int tid = threadIdx.x;

    for (int i = tid; i < 9*Cv*CH; i += 256) s_w1[i] = w1[i];
    for (int i = tid; i < 9*CH*CH; i += 256) s_w2[i] = w2[i];
    for (int i = tid; i < CH*CH;   i += 256) s_w3[i] = w3[i];
    if (tid < 32) { s_b1[tid] = b1[tid]; s_b2[tid] = b2[tid]; s_b3[tid] = b3[tid]; }

    // X tile 20x20 (halo 2), class -1 outside
    for (int p = tid; p < 400; p += 256) {
        int ly = p / 20, lx = p % 20;
        int gh = h0 + ly - 2, gw = w0 + lx - 2;
        s_x[p] = (gh >= 0 && gh < Hv && gw >= 0 && gw < Wv) ? X[(b*Hv+gh)*Wv+gw] : -1;
    }
    __syncthreads();

    // ---- phase 1: r1 on 18x18 (halo 1). warp lanes = co; warps stride pixels.
    {
        int co = tid & 31, wid = tid >> 5;
        for (int p = wid; p < 18*18; p += 8) {
            int lh = p / 18, lw = p % 18;       // r1 coords; X coords +1
            float acc = s_b1[co];
            #pragma unroll
            for (int dy = 0; dy < 3; dy++) {
                #pragma unroll
                for (int dx = 0; dx < 3; dx++) {
                    int c = s_x[(lh+dy)*20 + (lw+dx)];
                    if (c >= 0) acc += s_w1[((dy*3+dx)*Cv + c)*CH + co];
                }
            }
            s_r1[co*R1PITCH + lh*19 + lw] = fmaxf(acc, 0.f);
        }
    }
    __syncthreads();

    // ---- phase 2: conv2 (f32x2) + relu + conv3 (f32x2) on 16x16
    int lh = tid >> 4, lw = tid & 15;

    unsigned long long acc2[16];
    #pragma unroll
    for (int g = 0; g < 16; g++) acc2[g] = pack2(s_b2[2*g], s_b2[2*g+1]);

    #pragma unroll
    for (int pos = 0; pos < 9; pos++) {
        int dy = pos / 3, dx = pos % 3;
        const float* in_base = s_r1 + (lh+dy)*19 + (lw+dx);
        const ulonglong2* w_base = (const ulonglong2*)(s_w2 + pos*CH*CH);
        #pragma unroll 4
        for (int ci = 0; ci < CH; ci++) {
            float v = in_base[ci*R1PITCH];
            unsigned long long v2 = pack2(v, v);
            const ulonglong2* wp = w_base + ci*8;
            #pragma unroll
            for (int g = 0; g < 8; g++) {
                ulonglong2 wv = wp[g];
                ffma2(acc2[2*g],   v2, wv.x);
                ffma2(acc2[2*g+1], v2, wv.y);
            }
        }
    }

    float a[CH];
    #pragma unroll
    for (int g = 0; g < 16; g++) {
        float2 v = unpack2(acc2[g]);
        a[2*g]   = fmaxf(v.x, 0.f);
        a[2*g+1] = fmaxf(v.y, 0.f);
    }
    unsigned long long out2[16];
    #pragma unroll
    for (int g = 0; g < 16; g++) out2[g] = pack2(s_b3[2*g], s_b3[2*g+1]);
    {
        const ulonglong2* w3p = (const ulonglong2*)s_w3;
        #pragma unroll 4
        for (int ci = 0; ci < CH; ci++) {
            unsigned long long v2 = pack2(a[ci], a[ci]);
            const ulonglong2* wp = w3p + ci*8;
            #pragma unroll
            for (int g = 0; g < 8; g++) {
                ulonglong2 wv = wp[g];
                ffma2(out2[2*g],   v2, wv.x);
                ffma2(out2[2*g+1], v2, wv.y);
            }
        }
    }

    float4* dst = (float4*)(phi + (size_t)((b*Hv + h0+lh)*Wv + w0+lw)*CH);
    #pragma unroll
    for (int g = 0; g < 8; g++) {
        float2 lo = unpack2(out2[2*g]);
        float2 hi = unpack2(out2[2*g+1]);
        dst[g] = make_float4(lo.x, lo.y, hi.x, hi.y);
    }
}

// ============================================================================
// neighbor affinity — emits 2x-scaled weights (softmax beta folded in):
//   aff[p,d] = 2 * exp(-2 * ||phi[p]-phi[nbr]||^2) * valid
// ============================================================================
__device__ __forceinline__ float aff_edge(const float c[CH], const float* __restrict__ nb) {
    float d2 = 0.f;
    const float4* n4 = (const float4*)nb;
    #pragma unroll
    for (int g = 0; g < 8; g++) {
        float4 v = n4[g];
        float a = c[4*g+0] - v.x, b = c[4*g+1] - v.y;
        float e = c[4*g+2] - v.z, f = c[4*g+3] - v.w;
        d2 += a*a + b*b + e*e + f*f;
    }
    return 2.f * __expf(-2.f * d2);
}

__global__ __launch_bounds__(128) void aff_kernel(
    const float* __restrict__ phi, float* __restrict__ aff)
{
    int bh = blockIdx.x; int b = bh >> 7, h = bh & 127; int w = threadIdx.x;
    size_t pix = (size_t)(b*Hv + h)*Wv + w;
    float c[CH];
    const float4* c4 = (const float4*)(phi + pix*CH);
    #pragma unroll
    for (int g = 0; g < 8; g++) {
        float4 v = c4[g];
        c[4*g+0]=v.x; c[4*g+1]=v.y; c[4*g+2]=v.z; c[4*g+3]=v.w;
    }
    float4 wd;
    wd.x = (h+1 < Hv) ? aff_edge(c, phi + (pix + Wv)*CH) : 0.f;
    wd.y = (h   >= 1) ? aff_edge(c, phi + (pix - Wv)*CH) : 0.f;
    wd.z = (w+1 < Wv) ? aff_edge(c, phi + (pix + 1 )*CH) : 0.f;
    wd.w = (w   >= 1) ? aff_edge(c, phi + (pix - 1 )*CH) : 0.f;
    ((float4*)aff)[pix] = wd;
}

// ============================================================================
// fused 2x message-pass, f32x2 packed. A stored in smem as u64 channel-pairs
// [k2][pix]. Softmax temperature is pre-folded into aff (2x), and agg<=8 so
// exp never overflows -> no max-subtraction needed.
// ============================================================================
#define REG 20
#define REGPIX (REG*REG)           // 400
#define MP2_SMEM ((16*REGPIX*8)*2 + 4*REGPIX*4)   // 2x51200 + 6400 = 108800 B

__global__ __launch_bounds__(512, 2) void msgpass2_kernel(
    const float* __restrict__ Ain, int bstride,
    const float* __restrict__ aff, float* __restrict__ Aout)
{
    extern __shared__ float smem[];
    unsigned long long* sA = (unsigned long long*)smem;            // [16][400]
    unsigned long long* sB = sA + 16*REGPIX;                       // [16][400]
    float4*          s_aff = (float4*)(sB + 16*REGPIX);            // [400]

    int tid = threadIdx.x;
    int b   = blockIdx.z;
    int g0h = blockIdx.y*16 - 2;
    int g0w = blockIdx.x*16 - 2;

    const float* Abase = Ain + (size_t)b * bstride;

    for (int pix = tid; pix < REGPIX; pix += 512) {
        int y = pix / REG, x = pix % REG;
        int gh = g0h + y, gw = g0w + x;
        if (gh >= 0 && gh < Hv && gw >= 0 && gw < Wv) {
            const float4* src = (const float4*)(Abase + (size_t)(gh*Wv + gw)*Kv);
            #pragma unroll
            for (int g = 0; g < 8; g++) {
                float4 v = src[g];
                sA[(2*g  )*REGPIX + pix] = pack2(v.x, v.y);
                sA[(2*g+1)*REGPIX + pix] = pack2(v.z, v.w);
            }
            s_aff[pix] = ((const float4*)aff)[(size_t)(b*Hv + gh)*Wv + gw];
        } else {
            #pragma unroll
            for (int k2 = 0; k2 < 16; k2++) sA[k2*REGPIX + pix] = 0ull;
            s_aff[pix] = make_float4(0.f, 0.f, 0.f, 0.f);
        }
    }
    __syncthreads();

    // ---- pass 0: offset 1, 18x18 region, sA -> sB ----
    if (tid < 18*18) {
        int y = 1 + tid / 18, x = 1 + tid % 18;
        int pc = y*REG + x;
        float4 wd = s_aff[pc];
        unsigned long long wx = pack2(wd.x, wd.x), wy = pack2(wd.y, wd.y);
        unsigned long long wz = pack2(wd.z, wd.z), ww = pack2(wd.w, wd.w);
        float ex[Kv]; float s = 0.f;
        #pragma unroll
        for (int k2 = 0; k2 < 16; k2++) {
            const unsigned long long* row = sA + k2*REGPIX + pc;
            unsigned long long acc = mul2(wx, row[ REG]);
            ffma2(acc, wy, row[-REG]);
            ffma2(acc, wz, row[  1 ]);
            ffma2(acc, ww, row[ -1 ]);
            float2 p = unpack2(acc);
            float e0 = __expf(p.x), e1 = __expf(p.y);
            ex[2*k2] = e0; ex[2*k2+1] = e1; s += e0 + e1;
        }
        float inv = __fdividef(1.f, s);
        #pragma unroll
        for (int k2 = 0; k2 < 16; k2++)
            sB[k2*REGPIX + pc] = pack2(ex[2*k2]*inv, ex[2*k2+1]*inv);
    }
    __syncthreads();

    // ---- pass 1: offset 2, 16x16 interior, sB -> gmem direct ----
    if (tid < 256) {
        int ly = tid >> 4, lx = tid & 15;
        int pc = (2+ly)*REG + (2+lx);
        float4 wd = s_aff[pc];
        unsigned long long wx = pack2(wd.x, wd.x), wy = pack2(wd.y, wd.y);
        unsigned long long wz = pack2(wd.z, wd.z), ww = pack2(wd.w, wd.w);
        float ex[Kv]; float s = 0.f;
        #pragma unroll
        for (int k2 = 0; k2 < 16; k2++) {
            const unsigned long long* row = sB + k2*REGPIX + pc;
            unsigned long long acc = mul2(wx, row[ REG]);
            ffma2(acc, wy, row[-REG]);
            ffma2(acc, wz, row[  1 ]);
            ffma2(acc, ww, row[ -1 ]);
            float2 p = unpack2(acc);
            float e0 = __expf(p.x), e1 = __expf(p.y);
            ex[2*k2] = e0; ex[2*k2+1] = e1; s += e0 + e1;
        }
        float inv = __fdividef(1.f, s);
        int gh = g0h + 2 + ly, gw = g0w + 2 + lx;
        float4* dst = (float4*)(Aout + (size_t)((b*Hv + gh)*Wv + gw)*Kv);
        #pragma unroll
        for (int g = 0; g < 8; g++)
            dst[g] = make_float4(ex[4*g]*inv, ex[4*g+1]*inv, ex[4*g+2]*inv, ex[4*g+3]*inv);
    }
}

// ============================================================================
// pooling stage 1: per (b,h) row -> partials [mass, w_acc, w2_acc, cls0..9]
// ============================================================================
__global__ __launch_bounds__(256) void pool1_kernel(
    const float* __restrict__ A, const int* __restrict__ X, float* __restrict__ part)
{
    __shared__ int   s_x[Wv];
    __shared__ float s_red[3][8][Kv];
    __shared__ float s_cls[8][Kv][Cv];

    int bh = blockIdx.x; int b = bh >> 7, h = bh & 127;
    int tid = threadIdx.x;
    int k = tid & 31, wl = tid >> 5;

    if (tid < Wv) s_x[tid] = X[(b*Hv + h)*Wv + tid];
    __syncthreads();

    float mass = 0.f, wa = 0.f, w2a = 0.f;
    float cls[Cv];
    #pragma unroll
    for (int c = 0; c < Cv; c++) cls[c] = 0.f;

    #pragma unroll 1
    for (int it = 0; it < 16; it++) {
        int w = wl*16 + it;
        float a = A[((size_t)(b*Hv + h)*Wv + w)*Kv + k];
        float fw = (w + 0.5f) * (1.f/128.f);
        mass += a;
        wa  = fmaf(a, fw, wa);
        w2a = fmaf(a, fw*fw, w2a);
        int c = s_x[w];
        #pragma unroll
        for (int cc = 0; cc < Cv; cc++) cls[cc] += (c == cc) ? a : 0.f;
    }
    s_red[0][wl][k] = mass; s_red[1][wl][k] = wa; s_red[2][wl][k] = w2a;
    #pragma unroll
    for (int cc = 0; cc < Cv; cc++) s_cls[wl][k][cc] = cls[cc];
    __syncthreads();

    if (tid < Kv) {
        float m = 0.f, a1 = 0.f, a2 = 0.f, c10[Cv];
        #pragma unroll
        for (int cc = 0; cc < Cv; cc++) c10[cc] = 0.f;
        #pragma unroll
        for (int j = 0; j < 8; j++) {
            m  += s_red[0][j][tid];
            a1 += s_red[1][j][tid];
            a2 += s_red[2][j][tid];
            #pragma unroll
            for (int cc = 0; cc < Cv; cc++) c10[cc] += s_cls[j][tid][cc];
        }
        float* dst = part + ((size_t)(b*Hv + h)*Kv + tid)*13;
        dst[0] = m; dst[1] = a1; dst[2] = a2;
        #pragma unroll
        for (int cc = 0; cc < Cv; cc++) dst[3+cc] = c10[cc];
    }
}

// ============================================================================
// pooling stage 2: reduce over h, emit T (B,K,17)
// ============================================================================
__global__ __launch_bounds__(256) void pool2_kernel(
    const float* __restrict__ part, float* __restrict__ T)
{
    int i = blockIdx.x*blockDim.x + threadIdx.x;
    if (i >= Bv*Kv) return;
    int b = i / Kv, k = i % Kv;

    float macc=0.f, ha=0.f, h2a=0.f, wa=0.f, w2a=0.f, cls[Cv];
    #pragma unroll
    for (int cc = 0; cc < Cv; cc++) cls[cc] = 0.f;

    for (int h = 0; h < Hv; h++) {
        const float* p = part + ((size_t)(b*Hv + h)*Kv + k)*13;
        float m = p[0];
        float fh = (h + 0.5f) * (1.f/128.f);
        macc += m;
        ha  = fmaf(m, fh, ha);
        h2a = fmaf(m, fh*fh, h2a);
        wa  += p[1];
        w2a += p[2];
        #pragma unroll
        for (int cc = 0; cc < Cv; cc++) cls[cc] += p[3+cc];
    }
    float mass = macc + 1e-6f;
    float inv = 1.f / mass;
    float h_c = ha*inv, w_c = wa*inv;
    float h2 = h2a*inv, w2 = w2a*inv;
    float h_sd = sqrtf(fmaxf(h2 - h_c*h_c, 0.f) + 1e-6f);
    float w_sd = sqrtf(fmaxf(w2 - w_c*w_c, 0.f) + 1e-6f);

    float* t = T + (size_t)i * T_FEATS;
    t[0] = mass * (1.f/16384.f);
    t[1] = h_c; t[2] = w_c;
    #pragma unroll
    for (int cc = 0; cc < Cv; cc++) t[3+cc] = cls[cc]*inv;
    t[13] = h_c - h_sd; t[14] = h_c + h_sd;
    t[15] = w_c - w_sd; t[16] = w_c + w_sd;
}

// ============================================================================
// launch
// ============================================================================
extern "C" void kernel_launch(void* const* d_in, const int* in_sizes, int n_in,
                              void* d_out, int out_size)
{
    const int*   X  = (const int*)  d_in[0];
    const float* w1 = (const float*)d_in[1];
    const float* b1 = (const float*)d_in[2];
    const float* w2 = (const float*)d_in[3];
    const float* b2 = (const float*)d_in[4];
    const float* w3 = (const float*)d_in[5];
    const float* b3 = (const float*)d_in[6];

    float* outA = (float*)d_out;
    float* outT = (float*)d_out + A_ELEMS;

    float *r1, *phi, *aff, *A0, *part;
    cudaGetSymbolAddress((void**)&r1,   g_r1);
    cudaGetSymbolAddress((void**)&phi,  g_phi);
    cudaGetSymbolAddress((void**)&aff,  g_aff);
    cudaGetSymbolAddress((void**)&A0,   g_A0);
    cudaGetSymbolAddress((void**)&part, g_part);

    cudaFuncSetAttribute(conv123_kernel,  cudaFuncAttributeMaxDynamicSharedMemorySize, CONV_SMEM);
    cudaFuncSetAttribute(msgpass2_kernel, cudaFuncAttributeMaxDynamicSharedMemorySize, MP2_SMEM);

    // launch order: initA first so ncu (-s 5) captures a msgpass kernel
    initA_kernel<<<Hv, 128>>>(A0);                                            // 0
    conv123_kernel<<<dim3(Bv, Hv/16, Wv/16), 256, CONV_SMEM>>>(
        X, w1, b1, w2, b2, w3, b3, phi);                                      // 1
    aff_kernel<<<Bv*Hv, 128>>>(phi, aff);                                     // 2

    dim3 mpg(Wv/16, Hv/16, Bv);
    msgpass2_kernel<<<mpg, 512, MP2_SMEM>>>(A0,  0,         aff, r1);         // 3
    msgpass2_kernel<<<mpg, 512, MP2_SMEM>>>(r1,  Hv*Wv*Kv,  aff, phi);        // 4
    msgpass2_kernel<<<mpg, 512, MP2_SMEM>>>(phi, Hv*Wv*Kv,  aff, r1);         // 5  <- ncu target
    msgpass2_kernel<<<mpg, 512, MP2_SMEM>>>(r1,  Hv*Wv*Kv,  aff, outA);       // 6

    pool1_kernel<<<Bv*Hv, 256>>>(outA, X, part);                              // 7
    pool2_kernel<<<4, 256>>>(part, outT);                                     // 8
}